// round 2
// baseline (speedup 1.0000x reference)
#include <cuda_runtime.h>
#include <math.h>

// ---------------- scratch (device globals; no allocation) ----------------
#define MAX_M_LOGITS (1 << 18)   // 262144 floats = 1 MB, M = 100000 fits
#define MAX_G 4096

__device__ float g_logits[MAX_M_LOGITS];
__device__ float g_cgate[MAX_M_LOGITS];
__device__ float g_max_val;
__device__ float g_inv_sum;
__device__ int   g_seg[MAX_G + 1];
__device__ int   g_is64;

// ---------------- dtype detection (int64 vs int32 indices) ----------------
// jax int64 may be silently demoted to int32; sniff the buffer. Interpreting
// int32 data as int64 packs two values per word -> huge/negative numbers with
// overwhelming probability, so "all in [0, n_nodes)" identifies real int64.
__global__ void detect_kernel(const void* __restrict__ idx, int n_check,
                              long long n_nodes) {
    const long long* p = (const long long*)idx;
    int is64 = 1;
    for (int i = 0; i < n_check; i++) {
        long long v = p[i];
        if (v < 0 || v >= n_nodes) { is64 = 0; break; }
    }
    g_is64 = is64;
}

// ---------------- embed + logits: warp per motif ----------------
// embed[m] = mean_k n_emb[idx[m,k]]; logit[m] = dot(embed[m], att) / 10
__global__ void embed_kernel(const float* __restrict__ n_emb,
                             const float* __restrict__ att,
                             const void* __restrict__ midx,
                             float* __restrict__ embed_out,
                             int M, int K, int D) {
    int warp = (int)(((long long)blockIdx.x * blockDim.x + threadIdx.x) >> 5);
    int lane = threadIdx.x & 31;
    if (warp >= M) return;

    const bool is64 = (g_is64 != 0);
    const long long* mi64 = (const long long*)midx;
    const int*       mi32 = (const int*)midx;

    const float invK = 1.0f / (float)K;
    float* eout = embed_out + (long long)warp * D;
    float dot = 0.0f;

    if ((D & 127) == 0) {
        // float4 path: 32 lanes x float4 = 128 floats per chunk (one 512B row)
        for (int c = 0; c < D; c += 128) {
            float4 attv = ((const float4*)(att + c))[lane];
            float4 acc = make_float4(0.f, 0.f, 0.f, 0.f);
            for (int k0 = 0; k0 < K; k0 += 32) {
                int kn = min(32, K - k0);
                long long myidx = 0;
                if (lane < kn) {
                    long long pos = (long long)warp * K + k0 + lane;
                    myidx = is64 ? mi64[pos] : (long long)mi32[pos];
                }
                if (kn == 16) {
                    #pragma unroll 16
                    for (int k = 0; k < 16; k++) {
                        long long j = __shfl_sync(0xffffffffu, myidx, k);
                        float4 v = __ldg((const float4*)(n_emb + j * (long long)D + c) + lane);
                        acc.x += v.x; acc.y += v.y; acc.z += v.z; acc.w += v.w;
                    }
                } else {
                    for (int k = 0; k < kn; k++) {
                        long long j = __shfl_sync(0xffffffffu, myidx, k);
                        float4 v = __ldg((const float4*)(n_emb + j * (long long)D + c) + lane);
                        acc.x += v.x; acc.y += v.y; acc.z += v.z; acc.w += v.w;
                    }
                }
            }
            float4 e = make_float4(acc.x * invK, acc.y * invK, acc.z * invK, acc.w * invK);
            ((float4*)(eout + c))[lane] = e;
            dot += e.x * attv.x + e.y * attv.y + e.z * attv.z + e.w * attv.w;
        }
    } else {
        // scalar fallback: chunks of 32 floats
        for (int c = 0; c < D; c += 32) {
            int d = c + lane;
            float attv = (d < D) ? att[d] : 0.0f;
            float acc = 0.0f;
            for (int k0 = 0; k0 < K; k0 += 32) {
                int kn = min(32, K - k0);
                long long myidx = 0;
                if (lane < kn) {
                    long long pos = (long long)warp * K + k0 + lane;
                    myidx = is64 ? mi64[pos] : (long long)mi32[pos];
                }
                for (int k = 0; k < kn; k++) {
                    long long j = __shfl_sync(0xffffffffu, myidx, k);
                    if (d < D) acc += __ldg(n_emb + j * (long long)D + d);
                }
            }
            float e = acc * invK;
            if (d < D) { eout[d] = e; dot += e * attv; }
        }
    }

    // warp-reduce the dot product
    #pragma unroll
    for (int o = 16; o > 0; o >>= 1) dot += __shfl_xor_sync(0xffffffffu, dot, o);
    if (lane == 0) g_logits[warp] = dot / 10.0f;
}

// ---------------- deterministic softmax reduction (single block) ----------------
__global__ void softmax_reduce_kernel(int M) {
    const int tid = threadIdx.x;
    const int nthr = blockDim.x;
    __shared__ float sred[32];

    float mx = -3.402823466e38f;
    for (int i = tid; i < M; i += nthr) mx = fmaxf(mx, g_logits[i]);
    #pragma unroll
    for (int o = 16; o > 0; o >>= 1) mx = fmaxf(mx, __shfl_xor_sync(0xffffffffu, mx, o));
    if ((tid & 31) == 0) sred[tid >> 5] = mx;
    __syncthreads();
    if (tid < 32) {
        float v = (tid < (nthr >> 5)) ? sred[tid] : -3.402823466e38f;
        #pragma unroll
        for (int o = 16; o > 0; o >>= 1) v = fmaxf(v, __shfl_xor_sync(0xffffffffu, v, o));
        if (tid == 0) sred[0] = v;
    }
    __syncthreads();
    const float bmax = sred[0];
    __syncthreads();

    float s = 0.0f;
    for (int i = tid; i < M; i += nthr) s += expf(g_logits[i] - bmax);
    #pragma unroll
    for (int o = 16; o > 0; o >>= 1) s += __shfl_xor_sync(0xffffffffu, s, o);
    if ((tid & 31) == 0) sred[tid >> 5] = s;
    __syncthreads();
    if (tid < 32) {
        float v = (tid < (nthr >> 5)) ? sred[tid] : 0.0f;
        #pragma unroll
        for (int o = 16; o > 0; o >>= 1) v += __shfl_xor_sync(0xffffffffu, v, o);
        if (tid == 0) {
            g_max_val = bmax;
            g_inv_sum = 1.0f / v;
        }
    }
}

// ---------------- a[m], gate c[m], segment boundaries ----------------
__global__ void a_seg_kernel(const void* __restrict__ batch,
                             float* __restrict__ a_out, int M, int G) {
    int i = blockIdx.x * blockDim.x + threadIdx.x;
    if (i < M) {
        float a = expf(g_logits[i] - g_max_val) * g_inv_sum;
        a_out[i] = a;
        // sigmoid(1000*(a-0.1)); expf overflow -> inf -> c=0 (saturates correctly)
        g_cgate[i] = 1.0f / (1.0f + expf(-1000.0f * (a - 0.1f)));
    }
    if (i <= G) {
        const bool is64 = (g_is64 != 0);
        const long long* b64 = (const long long*)batch;
        const int*       b32 = (const int*)batch;
        int lo = 0, hi = M;
        while (lo < hi) {
            int mid = (lo + hi) >> 1;
            long long v = is64 ? b64[mid] : (long long)b32[mid];
            if (v < (long long)i) lo = mid + 1; else hi = mid;
        }
        g_seg[i] = lo;
    }
}

// ---------------- segment pooling: one block per graph ----------------
__global__ void pool_kernel(const float* __restrict__ embed,
                            const float* __restrict__ a_out,
                            float* __restrict__ mean_pool,
                            float* __restrict__ add_b,
                            float* __restrict__ add_inv,
                            int D) {
    const int g = blockIdx.x;
    const int start = g_seg[g];
    const int end   = g_seg[g + 1];
    const float inv_cnt = 1.0f / fmaxf((float)(end - start), 1.0f);

    for (int d = threadIdx.x; d < D; d += blockDim.x) {
        float sn = 0.f, sb = 0.f, se = 0.f;
        for (int m = start; m < end; m++) {
            float am = __ldg(a_out + m);
            float cm = __ldg(&g_cgate[m]);
            float e = embed[(long long)m * D + d];
            sn += e * cm;
            sb += e * am;
            se += e;
        }
        long long o = (long long)g * D + d;
        mean_pool[o] = sn * inv_cnt;
        add_b[o]     = sb;
        add_inv[o]   = se - sb;   // sum e*(1-a) = sum e - sum e*a
    }
}

// ---------------- launch ----------------
extern "C" void kernel_launch(void* const* d_in, const int* in_sizes, int n_in,
                              void* d_out, int out_size) {
    const float* n_emb = (const float*)d_in[0];
    const float* att   = (const float*)d_in[1];
    const void*  midx  = d_in[2];
    const void*  batch = d_in[3];

    const int D = in_sizes[1];
    const int M = in_sizes[3];
    const int K = in_sizes[2] / M;
    const long long n_nodes = (long long)in_sizes[0] / D;
    const int G = (int)(((long long)out_size - M - (long long)M * D) / (3LL * D));

    float* out       = (float*)d_out;
    float* a_out     = out;                          // [M]
    float* embed     = a_out + M;                    // [M, D]
    float* mean_pool = embed + (long long)M * D;     // [G, D]
    float* add_b     = mean_pool + (long long)G * D; // [G, D]
    float* add_inv   = add_b + (long long)G * D;     // [G, D]

    // 1) dtype sniff for the integer index buffers
    long long total_idx = (long long)M * K;
    int n_check = (int)min(32LL, total_idx / 2);
    detect_kernel<<<1, 1>>>(midx, n_check, n_nodes);

    // 2) embed + logits: warp per motif, 8 warps per block
    {
        int warps_per_block = 8;
        int blocks = (M + warps_per_block - 1) / warps_per_block;
        embed_kernel<<<blocks, warps_per_block * 32>>>(n_emb, att, midx, embed, M, K, D);
    }

    // 3) softmax max + sum (deterministic single block)
    softmax_reduce_kernel<<<1, 1024>>>(M);

    // 4) a[m], gate c[m], segment boundaries
    {
        int n = (M > G + 1) ? M : (G + 1);
        int blocks = (n + 255) / 256;
        a_seg_kernel<<<blocks, 256>>>(batch, a_out, M, G);
    }

    // 5) segment pooling (deterministic, atomic-free)
    pool_kernel<<<G, 128>>>(embed, a_out, mean_pool, add_b, add_inv, D);
}

// round 3
// speedup vs baseline: 1.2187x; 1.2187x over previous
#include <cuda_runtime.h>
#include <math.h>

// ---------------- scratch (device globals; no allocation) ----------------
#define MAX_M_LOGITS (1 << 18)   // 262144 floats, M = 100000 fits
#define MAX_G 4096
#define SMX_BLOCKS 128

__device__ float g_logits[MAX_M_LOGITS];
__device__ float g_cgate[MAX_M_LOGITS];
__device__ float g_pmax[SMX_BLOCKS];
__device__ float g_psum[SMX_BLOCKS];
__device__ float g_max_val;
__device__ float g_inv_sum;
__device__ int   g_seg[MAX_G + 1];
__device__ int   g_is64;

// ---------------- dtype detection (int64 vs int32 indices), warp-parallel ----
// jax int64 is often demoted to int32; int32 data read as int64 packs two
// values per word -> out-of-range with overwhelming probability.
__global__ void detect_kernel(const void* __restrict__ idx, int n_check,
                              long long n_nodes) {
    int lane = threadIdx.x;
    const long long* p = (const long long*)idx;
    int ok = 1;
    if (lane < n_check) {
        long long v = p[lane];
        ok = (v >= 0 && v < n_nodes) ? 1 : 0;
    }
    unsigned all = __all_sync(0xffffffffu, ok);
    if (lane == 0) g_is64 = all ? 1 : 0;
}

// ---------------- embed + logits: warp per motif ----------------
__global__ __launch_bounds__(256) void embed_kernel(
        const float* __restrict__ n_emb,
        const float* __restrict__ att,
        const void* __restrict__ midx,
        float* __restrict__ embed_out,
        int M, int K, int D) {
    int warp = (int)(((long long)blockIdx.x * blockDim.x + threadIdx.x) >> 5);
    int lane = threadIdx.x & 31;
    if (warp >= M) return;

    const bool is64 = (g_is64 != 0);
    const long long* mi64 = (const long long*)midx;
    const int*       mi32 = (const int*)midx;

    const float invK = 1.0f / (float)K;
    float* eout = embed_out + (long long)warp * D;
    float dot = 0.0f;

    if ((D & 127) == 0) {
        // float4 path: 32 lanes x float4 = 128 floats per chunk (512B row)
        for (int c = 0; c < D; c += 128) {
            float4 attv = ((const float4*)(att + c))[lane];
            float4 acc = make_float4(0.f, 0.f, 0.f, 0.f);
            for (int k0 = 0; k0 < K; k0 += 32) {
                int kn = min(32, K - k0);
                long long myidx = 0;
                if (lane < kn) {
                    long long pos = (long long)warp * K + k0 + lane;
                    myidx = is64 ? mi64[pos] : (long long)mi32[pos];
                }
                if (kn == 16) {
                    #pragma unroll 16
                    for (int k = 0; k < 16; k++) {
                        long long j = __shfl_sync(0xffffffffu, myidx, k);
                        float4 v = __ldg((const float4*)(n_emb + j * (long long)D + c) + lane);
                        acc.x += v.x; acc.y += v.y; acc.z += v.z; acc.w += v.w;
                    }
                } else {
                    for (int k = 0; k < kn; k++) {
                        long long j = __shfl_sync(0xffffffffu, myidx, k);
                        float4 v = __ldg((const float4*)(n_emb + j * (long long)D + c) + lane);
                        acc.x += v.x; acc.y += v.y; acc.z += v.z; acc.w += v.w;
                    }
                }
            }
            float4 e = make_float4(acc.x * invK, acc.y * invK, acc.z * invK, acc.w * invK);
            ((float4*)(eout + c))[lane] = e;
            dot += e.x * attv.x + e.y * attv.y + e.z * attv.z + e.w * attv.w;
        }
    } else {
        for (int c = 0; c < D; c += 32) {
            int d = c + lane;
            float attv = (d < D) ? att[d] : 0.0f;
            float acc = 0.0f;
            for (int k0 = 0; k0 < K; k0 += 32) {
                int kn = min(32, K - k0);
                long long myidx = 0;
                if (lane < kn) {
                    long long pos = (long long)warp * K + k0 + lane;
                    myidx = is64 ? mi64[pos] : (long long)mi32[pos];
                }
                for (int k = 0; k < kn; k++) {
                    long long j = __shfl_sync(0xffffffffu, myidx, k);
                    if (d < D) acc += __ldg(n_emb + j * (long long)D + d);
                }
            }
            float e = acc * invK;
            if (d < D) { eout[d] = e; dot += e * attv; }
        }
    }

    #pragma unroll
    for (int o = 16; o > 0; o >>= 1) dot += __shfl_xor_sync(0xffffffffu, dot, o);
    if (lane == 0) g_logits[warp] = dot / 10.0f;
}

// ---------------- online softmax: phase 1 (per-block partials) ----------------
__device__ __forceinline__ void smx_merge(float& m1, float& s1, float m2, float s2) {
    float M = fmaxf(m1, m2);
    float s = 0.0f;
    if (M > -3.0e38f) s = s1 * expf(m1 - M) + s2 * expf(m2 - M);
    m1 = M; s1 = s;
}

__global__ void softmax_p1_kernel(int M) {
    const int tid = threadIdx.x;
    const int stride = gridDim.x * blockDim.x;
    int i = blockIdx.x * blockDim.x + tid;

    float mx = -3.402823466e38f, sm = 0.0f;
    for (; i < M; i += stride) {
        float l = g_logits[i];
        if (l > mx) { sm = sm * expf(mx - l) + 1.0f; mx = l; }
        else        { sm += expf(l - mx); }
    }
    // warp merge
    #pragma unroll
    for (int o = 16; o > 0; o >>= 1) {
        float om = __shfl_xor_sync(0xffffffffu, mx, o);
        float os = __shfl_xor_sync(0xffffffffu, sm, o);
        smx_merge(mx, sm, om, os);
    }
    __shared__ float smx[8], ssm[8];
    if ((tid & 31) == 0) { smx[tid >> 5] = mx; ssm[tid >> 5] = sm; }
    __syncthreads();
    if (tid < 32) {
        int nw = blockDim.x >> 5;
        float m2 = (tid < nw) ? smx[tid] : -3.402823466e38f;
        float s2 = (tid < nw) ? ssm[tid] : 0.0f;
        #pragma unroll
        for (int o = 16; o > 0; o >>= 1) {
            float om = __shfl_xor_sync(0xffffffffu, m2, o);
            float os = __shfl_xor_sync(0xffffffffu, s2, o);
            smx_merge(m2, s2, om, os);
        }
        if (tid == 0) { g_pmax[blockIdx.x] = m2; g_psum[blockIdx.x] = s2; }
    }
}

// ---------------- online softmax: phase 2 (combine partials) ----------------
__global__ void softmax_p2_kernel(int nb) {
    const int tid = threadIdx.x;  // 128 threads
    float mx = (tid < nb) ? g_pmax[tid] : -3.402823466e38f;
    float sm = (tid < nb) ? g_psum[tid] : 0.0f;
    #pragma unroll
    for (int o = 16; o > 0; o >>= 1) {
        float om = __shfl_xor_sync(0xffffffffu, mx, o);
        float os = __shfl_xor_sync(0xffffffffu, sm, o);
        smx_merge(mx, sm, om, os);
    }
    __shared__ float smx[4], ssm[4];
    if ((tid & 31) == 0) { smx[tid >> 5] = mx; ssm[tid >> 5] = sm; }
    __syncthreads();
    if (tid == 0) {
        float m = smx[0], s = ssm[0];
        for (int w = 1; w < (blockDim.x >> 5); w++) smx_merge(m, s, smx[w], ssm[w]);
        g_max_val = m;
        g_inv_sum = 1.0f / s;
    }
}

// ---------------- a[m], gate c[m], segment boundaries (diff scan) ----------------
__global__ void a_seg_kernel(const void* __restrict__ batch,
                             float* __restrict__ a_out, int M, int G) {
    int i = blockIdx.x * blockDim.x + threadIdx.x;
    if (i >= M) return;

    float a = expf(g_logits[i] - g_max_val) * g_inv_sum;
    a_out[i] = a;
    // sigmoid(1000*(a-0.1)); expf overflow -> inf -> 0 (correct saturation)
    g_cgate[i] = 1.0f / (1.0f + expf(-1000.0f * (a - 0.1f)));

    // boundary diff scan: g_seg[v] = first index m with batch[m] >= v
    const bool is64 = (g_is64 != 0);
    const long long* b64 = (const long long*)batch;
    const int*       b32 = (const int*)batch;
    long long b0 = is64 ? b64[i] : (long long)b32[i];
    long long b1 = (i + 1 < M) ? (is64 ? b64[i + 1] : (long long)b32[i + 1])
                               : (long long)G;
    if (i == 0) {
        for (long long v = 0; v <= b0; v++) g_seg[v] = 0;
    }
    for (long long v = b0 + 1; v <= b1; v++) g_seg[v] = i + 1;
}

// ---------------- segment pooling: block per graph, 4 m-subranges ----------------
__global__ __launch_bounds__(512) void pool_kernel(
        const float* __restrict__ embed,
        const float* __restrict__ a_out,
        float* __restrict__ mean_pool,
        float* __restrict__ add_b,
        float* __restrict__ add_inv,
        int D) {
    const int g = blockIdx.x;
    const int start = g_seg[g];
    const int end   = g_seg[g + 1];
    const float inv_cnt = 1.0f / fmaxf((float)(end - start), 1.0f);

    const int nsub = blockDim.x / D;          // 4 when D=128
    const int d    = threadIdx.x % D;
    const int sub  = threadIdx.x / D;

    float sn = 0.f, sb = 0.f, se = 0.f;
    for (int m = start + sub; m < end; m += nsub) {
        float am = __ldg(a_out + m);
        float cm = g_cgate[m];
        float e  = __ldg(embed + (long long)m * D + d);
        sn += e * cm;
        sb += e * am;
        se += e;
    }

    extern __shared__ float sred[];           // [3 * nsub * D]
    float* r_sn = sred;
    float* r_sb = sred + nsub * D;
    float* r_se = sred + 2 * nsub * D;
    r_sn[sub * D + d] = sn;
    r_sb[sub * D + d] = sb;
    r_se[sub * D + d] = se;
    __syncthreads();

    if (sub == 0) {
        for (int s = 1; s < nsub; s++) {
            sn += r_sn[s * D + d];
            sb += r_sb[s * D + d];
            se += r_se[s * D + d];
        }
        long long o = (long long)g * D + d;
        mean_pool[o] = sn * inv_cnt;
        add_b[o]     = sb;
        add_inv[o]   = se - sb;   // sum e*(1-a) = sum e - sum e*a
    }
}

// ---------------- launch ----------------
extern "C" void kernel_launch(void* const* d_in, const int* in_sizes, int n_in,
                              void* d_out, int out_size) {
    const float* n_emb = (const float*)d_in[0];
    const float* att   = (const float*)d_in[1];
    const void*  midx  = d_in[2];
    const void*  batch = d_in[3];

    const int D = in_sizes[1];
    const int M = in_sizes[3];
    const int K = in_sizes[2] / M;
    const long long n_nodes = (long long)in_sizes[0] / D;
    const int G = (int)(((long long)out_size - M - (long long)M * D) / (3LL * D));

    float* out       = (float*)d_out;
    float* a_out     = out;                          // [M]
    float* embed     = a_out + M;                    // [M, D]
    float* mean_pool = embed + (long long)M * D;     // [G, D]
    float* add_b     = mean_pool + (long long)G * D; // [G, D]
    float* add_inv   = add_b + (long long)G * D;     // [G, D]

    // 1) dtype sniff (warp-parallel, one load round)
    long long total_idx = (long long)M * K;
    int n_check = (int)min(32LL, total_idx / 2);
    detect_kernel<<<1, 32>>>(midx, n_check, n_nodes);

    // 2) embed + logits: warp per motif
    {
        int warps_per_block = 8;
        int blocks = (M + warps_per_block - 1) / warps_per_block;
        embed_kernel<<<blocks, warps_per_block * 32>>>(n_emb, att, midx, embed, M, K, D);
    }

    // 3) two-phase deterministic online softmax
    softmax_p1_kernel<<<SMX_BLOCKS, 256>>>(M);
    softmax_p2_kernel<<<1, 128>>>(SMX_BLOCKS);

    // 4) a[m], gate c[m], segment boundaries (coalesced diff scan)
    a_seg_kernel<<<(M + 255) / 256, 256>>>(batch, a_out, M, G);

    // 5) segment pooling (deterministic, atomic-free)
    {
        int nsub = 4;
        int thr = nsub * D;              // 512 when D=128
        if (thr > 1024) { nsub = 1024 / D; thr = nsub * D; }
        size_t smem = (size_t)3 * nsub * D * sizeof(float);
        pool_kernel<<<G, thr, smem>>>(embed, a_out, mean_pool, add_b, add_inv, D);
    }
}

// round 4
// speedup vs baseline: 1.6547x; 1.3578x over previous
#include <cuda_runtime.h>
#include <math.h>

// ---------------- scratch (device globals; no allocation) ----------------
#define MAX_M_LOGITS (1 << 18)   // 262144 floats, M = 100000 fits
#define MAX_G 4096
#define SMX_BLOCKS 128

__device__ float g_logits[MAX_M_LOGITS];
__device__ float g_cgate[MAX_M_LOGITS];
__device__ float g_pmax[SMX_BLOCKS];
__device__ float g_psum[SMX_BLOCKS];
__device__ int   g_seg[MAX_G + 1];

// ---------------- embed + logits: warp per motif ----------------
// Per-warp dtype sniff: read K/2 int64s from this warp's own K*4-byte window
// (in-bounds whichever dtype the buffer really is). int32 data seen as int64
// packs two indices per word -> out of [0, n_nodes) with prob ~1.
__global__ __launch_bounds__(256) void embed_kernel(
        const float* __restrict__ n_emb,
        const float* __restrict__ att,
        const void* __restrict__ midx,
        float* __restrict__ embed_out,
        int M, int K, int D, long long n_nodes) {
    int warp = (int)(((long long)blockIdx.x * blockDim.x + threadIdx.x) >> 5);
    int lane = threadIdx.x & 31;
    if (warp >= M) return;

    const long long* mi64 = (const long long*)midx;
    const int*       mi32 = (const int*)midx;

    // dtype sniff (K even; K=16 here)
    int ok = 1;
    if (lane < (K >> 1)) {
        long long v = __ldcs(mi64 + (long long)warp * (K >> 1) + lane);
        ok = (v >= 0 && v < n_nodes) ? 1 : 0;
    }
    const bool is64 = (__all_sync(0xffffffffu, ok) != 0);

    const float invK = 1.0f / (float)K;
    float* eout = embed_out + (long long)warp * D;
    float dot = 0.0f;

    const unsigned rowbytes = (unsigned)(D * 4);
    const bool fit32 = (n_nodes * (long long)rowbytes) < 0x7fffffffLL;

    if ((D & 127) == 0 && fit32) {
        // float4 path: 32 lanes x float4 = 128 floats per chunk (512B row)
        const char* base = (const char*)n_emb;
        // this lane's neighbor byte-offset (lane < K)
        unsigned myoff = 0;
        if (lane < K && K <= 32) {
            long long pos = (long long)warp * K + lane;
            long long j = is64 ? __ldcs(mi64 + pos) : (long long)__ldcs(mi32 + pos);
            myoff = (unsigned)j * rowbytes;
        }
        for (int c = 0; c < D; c += 128) {
            float4 attv = ((const float4*)(att + c))[lane];
            float4 acc = make_float4(0.f, 0.f, 0.f, 0.f);
            if (K == 16) {
                #pragma unroll 16
                for (int k = 0; k < 16; k++) {
                    unsigned off = __shfl_sync(0xffffffffu, myoff, k);
                    float4 v = __ldg((const float4*)(base + off + c * 4) + lane);
                    acc.x += v.x; acc.y += v.y; acc.z += v.z; acc.w += v.w;
                }
            } else {
                for (int k0 = 0; k0 < K; k0 += 32) {
                    int kn = min(32, K - k0);
                    unsigned o2 = 0;
                    if (lane < kn) {
                        long long pos = (long long)warp * K + k0 + lane;
                        long long j = is64 ? __ldcs(mi64 + pos) : (long long)__ldcs(mi32 + pos);
                        o2 = (unsigned)j * rowbytes;
                    }
                    for (int k = 0; k < kn; k++) {
                        unsigned off = __shfl_sync(0xffffffffu, o2, k);
                        float4 v = __ldg((const float4*)(base + off + c * 4) + lane);
                        acc.x += v.x; acc.y += v.y; acc.z += v.z; acc.w += v.w;
                    }
                }
            }
            float4 e = make_float4(acc.x * invK, acc.y * invK, acc.z * invK, acc.w * invK);
            __stcs((float4*)(eout + c) + lane, e);   // evict-first: keep table in L2
            dot += e.x * attv.x + e.y * attv.y + e.z * attv.z + e.w * attv.w;
        }
    } else {
        // generic scalar fallback
        for (int c = 0; c < D; c += 32) {
            int d = c + lane;
            float attv = (d < D) ? att[d] : 0.0f;
            float acc = 0.0f;
            for (int k0 = 0; k0 < K; k0 += 32) {
                int kn = min(32, K - k0);
                long long myidx = 0;
                if (lane < kn) {
                    long long pos = (long long)warp * K + k0 + lane;
                    myidx = is64 ? mi64[pos] : (long long)mi32[pos];
                }
                for (int k = 0; k < kn; k++) {
                    long long j = __shfl_sync(0xffffffffu, myidx, k);
                    if (d < D) acc += __ldg(n_emb + j * (long long)D + d);
                }
            }
            float e = acc * invK;
            if (d < D) { eout[d] = e; dot += e * attv; }
        }
    }

    #pragma unroll
    for (int o = 16; o > 0; o >>= 1) dot += __shfl_xor_sync(0xffffffffu, dot, o);
    if (lane == 0) g_logits[warp] = dot / 10.0f;
}

// ---------------- online softmax: phase 1 (per-block partials) ----------------
__device__ __forceinline__ void smx_merge(float& m1, float& s1, float m2, float s2) {
    float M = fmaxf(m1, m2);
    float s = 0.0f;
    if (M > -3.0e38f) s = s1 * expf(m1 - M) + s2 * expf(m2 - M);
    m1 = M; s1 = s;
}

__global__ void softmax_p1_kernel(int M) {
    const int tid = threadIdx.x;
    const int stride = gridDim.x * blockDim.x;
    int i = blockIdx.x * blockDim.x + tid;

    float mx = -3.402823466e38f, sm = 0.0f;
    for (; i < M; i += stride) {
        float l = g_logits[i];
        if (l > mx) { sm = sm * expf(mx - l) + 1.0f; mx = l; }
        else        { sm += expf(l - mx); }
    }
    #pragma unroll
    for (int o = 16; o > 0; o >>= 1) {
        float om = __shfl_xor_sync(0xffffffffu, mx, o);
        float os = __shfl_xor_sync(0xffffffffu, sm, o);
        smx_merge(mx, sm, om, os);
    }
    __shared__ float smx[8], ssm[8];
    if ((tid & 31) == 0) { smx[tid >> 5] = mx; ssm[tid >> 5] = sm; }
    __syncthreads();
    if (tid < 32) {
        int nw = blockDim.x >> 5;
        float m2 = (tid < nw) ? smx[tid] : -3.402823466e38f;
        float s2 = (tid < nw) ? ssm[tid] : 0.0f;
        #pragma unroll
        for (int o = 16; o > 0; o >>= 1) {
            float om = __shfl_xor_sync(0xffffffffu, m2, o);
            float os = __shfl_xor_sync(0xffffffffu, s2, o);
            smx_merge(m2, s2, om, os);
        }
        if (tid == 0) { g_pmax[blockIdx.x] = m2; g_psum[blockIdx.x] = s2; }
    }
}

// ------- a[m], gate c[m], seg boundaries; fuses the partial combine -------
__global__ __launch_bounds__(256) void a_seg_kernel(
        const void* __restrict__ batch,
        float* __restrict__ a_out, int M, int G) {
    const int tid = threadIdx.x;
    __shared__ float sm_m[4], sm_s[4];
    __shared__ float s_fin[2];
    __shared__ int   s_b64;

    // combine the 128 softmax partials (redundant per block; replaces a launch)
    if (tid < SMX_BLOCKS) {
        float m = g_pmax[tid], s = g_psum[tid];
        #pragma unroll
        for (int o = 16; o > 0; o >>= 1) {
            float om = __shfl_xor_sync(0xffffffffu, m, o);
            float os = __shfl_xor_sync(0xffffffffu, s, o);
            smx_merge(m, s, om, os);
        }
        if ((tid & 31) == 0) { sm_m[tid >> 5] = m; sm_s[tid >> 5] = s; }
    }
    // batch dtype sniff from the END of the sorted array (start may be all 0s)
    if (tid >= 128 && tid < 160) {
        int lane = tid & 31;
        int ok = 1;
        if (lane < 8) {
            long long p = (long long)(M >> 1) - 1 - lane;
            if (p >= 0) {
                long long v = ((const long long*)batch)[p];
                ok = (v >= 0 && v < (long long)G) ? 1 : 0;
            }
        }
        unsigned all = __all_sync(0xffffffffu, ok);
        if (lane == 0) s_b64 = all ? 1 : 0;
    }
    __syncthreads();
    if (tid == 0) {
        float m = sm_m[0], s = sm_s[0];
        #pragma unroll
        for (int w = 1; w < 4; w++) smx_merge(m, s, sm_m[w], sm_s[w]);
        s_fin[0] = m; s_fin[1] = 1.0f / s;
    }
    __syncthreads();
    const float gmax = s_fin[0];
    const float ginv = s_fin[1];
    const bool  is64 = (s_b64 != 0);

    int i = blockIdx.x * blockDim.x + tid;
    if (i >= M) return;

    float a = expf(g_logits[i] - gmax) * ginv;
    a_out[i] = a;
    // sigmoid(1000*(a-0.1)); expf overflow -> inf -> 0 (correct saturation)
    g_cgate[i] = 1.0f / (1.0f + expf(-1000.0f * (a - 0.1f)));

    // boundary diff scan: g_seg[v] = first index m with batch[m] >= v
    const long long* b64 = (const long long*)batch;
    const int*       b32 = (const int*)batch;
    long long b0 = is64 ? b64[i] : (long long)b32[i];
    long long b1 = (i + 1 < M) ? (is64 ? b64[i + 1] : (long long)b32[i + 1])
                               : (long long)G;
    if (i == 0) {
        for (long long v = 0; v <= b0; v++) g_seg[v] = 0;
    }
    for (long long v = b0 + 1; v <= b1; v++) g_seg[v] = i + 1;
}

// ---------------- segment pooling: block per graph, 4 m-subranges ----------------
__global__ __launch_bounds__(512) void pool_kernel(
        const float* __restrict__ embed,
        const float* __restrict__ a_out,
        float* __restrict__ mean_pool,
        float* __restrict__ add_b,
        float* __restrict__ add_inv,
        int D) {
    const int g = blockIdx.x;
    const int start = g_seg[g];
    const int end   = g_seg[g + 1];
    const float inv_cnt = 1.0f / fmaxf((float)(end - start), 1.0f);

    const int nsub = blockDim.x / D;          // 4 when D=128
    const int d    = threadIdx.x % D;
    const int sub  = threadIdx.x / D;

    float sn = 0.f, sb = 0.f, se = 0.f;
    for (int m = start + sub; m < end; m += nsub) {
        float am = __ldg(a_out + m);
        float cm = g_cgate[m];
        float e  = __ldcs(embed + (long long)m * D + d);  // one-time stream
        sn += e * cm;
        sb += e * am;
        se += e;
    }

    extern __shared__ float sred[];           // [3 * nsub * D]
    float* r_sn = sred;
    float* r_sb = sred + nsub * D;
    float* r_se = sred + 2 * nsub * D;
    r_sn[sub * D + d] = sn;
    r_sb[sub * D + d] = sb;
    r_se[sub * D + d] = se;
    __syncthreads();

    if (sub == 0) {
        for (int s = 1; s < nsub; s++) {
            sn += r_sn[s * D + d];
            sb += r_sb[s * D + d];
            se += r_se[s * D + d];
        }
        long long o = (long long)g * D + d;
        mean_pool[o] = sn * inv_cnt;
        add_b[o]     = sb;
        add_inv[o]   = se - sb;   // sum e*(1-a) = sum e - sum e*a
    }
}

// ---------------- launch ----------------
extern "C" void kernel_launch(void* const* d_in, const int* in_sizes, int n_in,
                              void* d_out, int out_size) {
    const float* n_emb = (const float*)d_in[0];
    const float* att   = (const float*)d_in[1];
    const void*  midx  = d_in[2];
    const void*  batch = d_in[3];

    const int D = in_sizes[1];
    const int M = in_sizes[3];
    const int K = in_sizes[2] / M;
    const long long n_nodes = (long long)in_sizes[0] / D;
    const int G = (int)(((long long)out_size - M - (long long)M * D) / (3LL * D));

    float* out       = (float*)d_out;
    float* a_out     = out;                          // [M]
    float* embed     = a_out + M;                    // [M, D]
    float* mean_pool = embed + (long long)M * D;     // [G, D]
    float* add_b     = mean_pool + (long long)G * D; // [G, D]
    float* add_inv   = add_b + (long long)G * D;     // [G, D]

    // 1) embed + logits (dtype sniff fused, warp per motif)
    {
        int warps_per_block = 8;
        int blocks = (M + warps_per_block - 1) / warps_per_block;
        embed_kernel<<<blocks, warps_per_block * 32>>>(n_emb, att, midx, embed,
                                                       M, K, D, n_nodes);
    }

    // 2) softmax partials
    softmax_p1_kernel<<<SMX_BLOCKS, 256>>>(M);

    // 3) combine + a[m], gate, segment boundaries
    a_seg_kernel<<<(M + 255) / 256, 256>>>(batch, a_out, M, G);

    // 4) segment pooling (deterministic, atomic-free)
    {
        int nsub = 4;
        int thr = nsub * D;              // 512 when D=128
        if (thr > 1024) { nsub = 1024 / D; thr = nsub * D; }
        if (thr < 32) { nsub = 1; thr = D; }
        size_t smem = (size_t)3 * nsub * D * sizeof(float);
        pool_kernel<<<G, thr, smem>>>(embed, a_out, mean_pool, add_b, add_inv, D);
    }
}

// round 5
// speedup vs baseline: 2.1994x; 1.3291x over previous
#include <cuda_runtime.h>
#include <math.h>

// ---------------- scratch (device globals; no allocation) ----------------
#define MAX_M_LOGITS (1 << 18)   // 262144 floats, M = 100000 fits
#define MAX_G 4096
#define SMX_BLOCKS 128
#define POOL_SCRATCH_FLOATS (1 << 23)   // 8M floats = 32 MB partial-sum scratch

__device__ float g_logits[MAX_M_LOGITS];
__device__ float g_cgate[MAX_M_LOGITS];
__device__ float g_pmax[SMX_BLOCKS];
__device__ float g_psum[SMX_BLOCKS];
__device__ int   g_seg[MAX_G + 1];
__device__ float g_part[POOL_SCRATCH_FLOATS];

// ---------------- embed + logits: warp per motif ----------------
// Per-warp dtype sniff: read K/2 int64s from this warp's own K*4-byte window
// (in-bounds whichever dtype the buffer really is). int32 data seen as int64
// packs two indices per word -> out of [0, n_nodes) with prob ~1.
__global__ __launch_bounds__(256) void embed_kernel(
        const float* __restrict__ n_emb,
        const float* __restrict__ att,
        const void* __restrict__ midx,
        float* __restrict__ embed_out,
        int M, int K, int D, long long n_nodes) {
    int warp = (int)(((long long)blockIdx.x * blockDim.x + threadIdx.x) >> 5);
    int lane = threadIdx.x & 31;
    if (warp >= M) return;

    const long long* mi64 = (const long long*)midx;
    const int*       mi32 = (const int*)midx;

    // dtype sniff (K even; K=16 here)
    int ok = 1;
    if (lane < (K >> 1)) {
        long long v = __ldcs(mi64 + (long long)warp * (K >> 1) + lane);
        ok = (v >= 0 && v < n_nodes) ? 1 : 0;
    }
    const bool is64 = (__all_sync(0xffffffffu, ok) != 0);

    const float invK = 1.0f / (float)K;
    float* eout = embed_out + (long long)warp * D;
    float dot = 0.0f;

    const unsigned rowbytes = (unsigned)(D * 4);
    const bool fit32 = (n_nodes * (long long)rowbytes) < 0x7fffffffLL;

    if ((D & 127) == 0 && fit32) {
        const char* base = (const char*)n_emb;
        unsigned myoff = 0;
        if (lane < K && K <= 32) {
            long long pos = (long long)warp * K + lane;
            long long j = is64 ? __ldcs(mi64 + pos) : (long long)__ldcs(mi32 + pos);
            myoff = (unsigned)j * rowbytes;
        }
        for (int c = 0; c < D; c += 128) {
            float4 attv = ((const float4*)(att + c))[lane];
            float4 acc = make_float4(0.f, 0.f, 0.f, 0.f);
            if (K == 16) {
                #pragma unroll 16
                for (int k = 0; k < 16; k++) {
                    unsigned off = __shfl_sync(0xffffffffu, myoff, k);
                    float4 v = __ldg((const float4*)(base + off + c * 4) + lane);
                    acc.x += v.x; acc.y += v.y; acc.z += v.z; acc.w += v.w;
                }
            } else {
                for (int k0 = 0; k0 < K; k0 += 32) {
                    int kn = min(32, K - k0);
                    unsigned o2 = 0;
                    if (lane < kn) {
                        long long pos = (long long)warp * K + k0 + lane;
                        long long j = is64 ? __ldcs(mi64 + pos) : (long long)__ldcs(mi32 + pos);
                        o2 = (unsigned)j * rowbytes;
                    }
                    for (int k = 0; k < kn; k++) {
                        unsigned off = __shfl_sync(0xffffffffu, o2, k);
                        float4 v = __ldg((const float4*)(base + off + c * 4) + lane);
                        acc.x += v.x; acc.y += v.y; acc.z += v.z; acc.w += v.w;
                    }
                }
            }
            float4 e = make_float4(acc.x * invK, acc.y * invK, acc.z * invK, acc.w * invK);
            __stcs((float4*)(eout + c) + lane, e);   // evict-first: keep table in L2
            dot += e.x * attv.x + e.y * attv.y + e.z * attv.z + e.w * attv.w;
        }
    } else {
        for (int c = 0; c < D; c += 32) {
            int d = c + lane;
            float attv = (d < D) ? att[d] : 0.0f;
            float acc = 0.0f;
            for (int k0 = 0; k0 < K; k0 += 32) {
                int kn = min(32, K - k0);
                long long myidx = 0;
                if (lane < kn) {
                    long long pos = (long long)warp * K + k0 + lane;
                    myidx = is64 ? mi64[pos] : (long long)mi32[pos];
                }
                for (int k = 0; k < kn; k++) {
                    long long j = __shfl_sync(0xffffffffu, myidx, k);
                    if (d < D) acc += __ldg(n_emb + j * (long long)D + d);
                }
            }
            float e = acc * invK;
            if (d < D) { eout[d] = e; dot += e * attv; }
        }
    }

    #pragma unroll
    for (int o = 16; o > 0; o >>= 1) dot += __shfl_xor_sync(0xffffffffu, dot, o);
    if (lane == 0) g_logits[warp] = dot / 10.0f;
}

// ---------------- online softmax: phase 1 (per-block partials) ----------------
__device__ __forceinline__ void smx_merge(float& m1, float& s1, float m2, float s2) {
    float M = fmaxf(m1, m2);
    float s = 0.0f;
    if (M > -3.0e38f) s = s1 * expf(m1 - M) + s2 * expf(m2 - M);
    m1 = M; s1 = s;
}

__global__ void softmax_p1_kernel(int M) {
    const int tid = threadIdx.x;
    const int stride = gridDim.x * blockDim.x;
    int i = blockIdx.x * blockDim.x + tid;

    float mx = -3.402823466e38f, sm = 0.0f;
    for (; i < M; i += stride) {
        float l = g_logits[i];
        if (l > mx) { sm = sm * expf(mx - l) + 1.0f; mx = l; }
        else        { sm += expf(l - mx); }
    }
    #pragma unroll
    for (int o = 16; o > 0; o >>= 1) {
        float om = __shfl_xor_sync(0xffffffffu, mx, o);
        float os = __shfl_xor_sync(0xffffffffu, sm, o);
        smx_merge(mx, sm, om, os);
    }
    __shared__ float smx[8], ssm[8];
    if ((tid & 31) == 0) { smx[tid >> 5] = mx; ssm[tid >> 5] = sm; }
    __syncthreads();
    if (tid < 32) {
        int nw = blockDim.x >> 5;
        float m2 = (tid < nw) ? smx[tid] : -3.402823466e38f;
        float s2 = (tid < nw) ? ssm[tid] : 0.0f;
        #pragma unroll
        for (int o = 16; o > 0; o >>= 1) {
            float om = __shfl_xor_sync(0xffffffffu, m2, o);
            float os = __shfl_xor_sync(0xffffffffu, s2, o);
            smx_merge(m2, s2, om, os);
        }
        if (tid == 0) { g_pmax[blockIdx.x] = m2; g_psum[blockIdx.x] = s2; }
    }
}

// ------- a[m], gate c[m], seg boundaries; fuses the partial combine -------
__global__ __launch_bounds__(256) void a_seg_kernel(
        const void* __restrict__ batch,
        float* __restrict__ a_out, int M, int G) {
    const int tid = threadIdx.x;
    __shared__ float sm_m[4], sm_s[4];
    __shared__ float s_fin[2];
    __shared__ int   s_b64;

    if (tid < SMX_BLOCKS) {
        float m = g_pmax[tid], s = g_psum[tid];
        #pragma unroll
        for (int o = 16; o > 0; o >>= 1) {
            float om = __shfl_xor_sync(0xffffffffu, m, o);
            float os = __shfl_xor_sync(0xffffffffu, s, o);
            smx_merge(m, s, om, os);
        }
        if ((tid & 31) == 0) { sm_m[tid >> 5] = m; sm_s[tid >> 5] = s; }
    }
    // batch dtype sniff from the END of the sorted array (start may be all 0s)
    if (tid >= 128 && tid < 160) {
        int lane = tid & 31;
        int ok = 1;
        if (lane < 8) {
            long long p = (long long)(M >> 1) - 1 - lane;
            if (p >= 0) {
                long long v = ((const long long*)batch)[p];
                ok = (v >= 0 && v < (long long)G) ? 1 : 0;
            }
        }
        unsigned all = __all_sync(0xffffffffu, ok);
        if (lane == 0) s_b64 = all ? 1 : 0;
    }
    __syncthreads();
    if (tid == 0) {
        float m = sm_m[0], s = sm_s[0];
        #pragma unroll
        for (int w = 1; w < 4; w++) smx_merge(m, s, sm_m[w], sm_s[w]);
        s_fin[0] = m; s_fin[1] = 1.0f / s;
    }
    __syncthreads();
    const float gmax = s_fin[0];
    const float ginv = s_fin[1];
    const bool  is64 = (s_b64 != 0);

    int i = blockIdx.x * blockDim.x + tid;
    if (i >= M) return;

    float a = expf(g_logits[i] - gmax) * ginv;
    a_out[i] = a;
    g_cgate[i] = 1.0f / (1.0f + expf(-1000.0f * (a - 0.1f)));

    const long long* b64 = (const long long*)batch;
    const int*       b32 = (const int*)batch;
    long long b0 = is64 ? b64[i] : (long long)b32[i];
    long long b1 = (i + 1 < M) ? (is64 ? b64[i + 1] : (long long)b32[i + 1])
                               : (long long)G;
    if (i == 0) {
        for (long long v = 0; v <= b0; v++) g_seg[v] = 0;
    }
    for (long long v = b0 + 1; v <= b1; v++) g_seg[v] = i + 1;
}

// ---------------- pool phase 1: (graph, chunk) grid, warp-per-row ----------------
// Requires D % 4 == 0 and D <= 128 (one warp covers a row in float4s).
__global__ __launch_bounds__(512) void pool_p1_kernel(
        const float* __restrict__ embed,
        const float* __restrict__ a_out,
        int D, int C) {
    const int g = blockIdx.x;
    const int c = blockIdx.y;
    const int start = g_seg[g];
    const int end   = g_seg[g + 1];
    const int lane = threadIdx.x & 31;
    const int w    = threadIdx.x >> 5;       // 16 warps
    const int nd4  = D >> 2;

    float4 an = make_float4(0.f, 0.f, 0.f, 0.f);
    float4 ab = an, ae = an;

    if (lane < nd4) {
        for (int m = start + c * 16 + w; m < end; m += C * 16) {
            float am = __ldg(a_out + m);
            float cm = g_cgate[m];
            float4 e = __ldcs((const float4*)(embed + (long long)m * D) + lane);
            an.x += e.x * cm; an.y += e.y * cm; an.z += e.z * cm; an.w += e.w * cm;
            ab.x += e.x * am; ab.y += e.y * am; ab.z += e.z * am; ab.w += e.w * am;
            ae.x += e.x;      ae.y += e.y;      ae.z += e.z;      ae.w += e.w;
        }
    }

    extern __shared__ float sred[];          // [16][3][D]
    if (lane < nd4) {
        ((float4*)(sred + (w * 3 + 0) * D))[lane] = an;
        ((float4*)(sred + (w * 3 + 1) * D))[lane] = ab;
        ((float4*)(sred + (w * 3 + 2) * D))[lane] = ae;
    }
    __syncthreads();

    const int t = threadIdx.x;
    if (t < 3 * D) {
        const int r = t / D, d = t % D;
        float s = 0.f;
        #pragma unroll 4
        for (int w2 = 0; w2 < 16; w2++) s += sred[(w2 * 3 + r) * D + d];
        g_part[(((long long)g * C + c) * 3 + r) * D + d] = s;
    }
}

// ---------------- pool phase 2: combine chunk partials ----------------
__global__ void pool_p2_kernel(float* __restrict__ mean_pool,
                               float* __restrict__ add_b,
                               float* __restrict__ add_inv,
                               int D, int C) {
    const int g = blockIdx.x;
    const int d = threadIdx.x;
    if (d >= D) return;
    const int cnt = g_seg[g + 1] - g_seg[g];
    const float inv_cnt = 1.0f / fmaxf((float)cnt, 1.0f);

    float sn = 0.f, sb = 0.f, se = 0.f;
    for (int c = 0; c < C; c++) {
        const float* p = g_part + (((long long)g * C + c) * 3) * D;
        sn += p[d];
        sb += p[D + d];
        se += p[2 * D + d];
    }
    long long o = (long long)g * D + d;
    mean_pool[o] = sn * inv_cnt;
    add_b[o]     = sb;
    add_inv[o]   = se - sb;
}

// ---------------- pool fallback: block per graph (generic D) ----------------
__global__ __launch_bounds__(512) void pool_kernel(
        const float* __restrict__ embed,
        const float* __restrict__ a_out,
        float* __restrict__ mean_pool,
        float* __restrict__ add_b,
        float* __restrict__ add_inv,
        int D) {
    const int g = blockIdx.x;
    const int start = g_seg[g];
    const int end   = g_seg[g + 1];
    const float inv_cnt = 1.0f / fmaxf((float)(end - start), 1.0f);

    const int nsub = blockDim.x / D;
    const int d    = threadIdx.x % D;
    const int sub  = threadIdx.x / D;

    float sn = 0.f, sb = 0.f, se = 0.f;
    for (int m = start + sub; m < end; m += nsub) {
        float am = __ldg(a_out + m);
        float cm = g_cgate[m];
        float e  = __ldcs(embed + (long long)m * D + d);
        sn += e * cm;
        sb += e * am;
        se += e;
    }

    extern __shared__ float sred[];
    float* r_sn = sred;
    float* r_sb = sred + nsub * D;
    float* r_se = sred + 2 * nsub * D;
    r_sn[sub * D + d] = sn;
    r_sb[sub * D + d] = sb;
    r_se[sub * D + d] = se;
    __syncthreads();

    if (sub == 0) {
        for (int s = 1; s < nsub; s++) {
            sn += r_sn[s * D + d];
            sb += r_sb[s * D + d];
            se += r_se[s * D + d];
        }
        long long o = (long long)g * D + d;
        mean_pool[o] = sn * inv_cnt;
        add_b[o]     = sb;
        add_inv[o]   = se - sb;
    }
}

// ---------------- launch ----------------
extern "C" void kernel_launch(void* const* d_in, const int* in_sizes, int n_in,
                              void* d_out, int out_size) {
    const float* n_emb = (const float*)d_in[0];
    const float* att   = (const float*)d_in[1];
    const void*  midx  = d_in[2];
    const void*  batch = d_in[3];

    const int D = in_sizes[1];
    const int M = in_sizes[3];
    const int K = in_sizes[2] / M;
    const long long n_nodes = (long long)in_sizes[0] / D;
    const int G = (int)(((long long)out_size - M - (long long)M * D) / (3LL * D));

    float* out       = (float*)d_out;
    float* a_out     = out;                          // [M]
    float* embed     = a_out + M;                    // [M, D]
    float* mean_pool = embed + (long long)M * D;     // [G, D]
    float* add_b     = mean_pool + (long long)G * D; // [G, D]
    float* add_inv   = add_b + (long long)G * D;     // [G, D]

    // 1) embed + logits (dtype sniff fused, warp per motif)
    {
        int warps_per_block = 8;
        int blocks = (M + warps_per_block - 1) / warps_per_block;
        embed_kernel<<<blocks, warps_per_block * 32>>>(n_emb, att, midx, embed,
                                                       M, K, D, n_nodes);
    }

    // 2) softmax partials
    softmax_p1_kernel<<<SMX_BLOCKS, 256>>>(M);

    // 3) combine + a[m], gate, segment boundaries
    a_seg_kernel<<<(M + 255) / 256, 256>>>(batch, a_out, M, G);

    // 4) segment pooling (deterministic, atomic-free)
    if ((D & 3) == 0 && D <= 128) {
        int C = 8;
        while (C > 1 && (long long)G * C * 3 * D > POOL_SCRATCH_FLOATS) C >>= 1;
        size_t smem1 = (size_t)16 * 3 * D * sizeof(float);
        dim3 grid1(G, C);
        pool_p1_kernel<<<grid1, 512, smem1>>>(embed, a_out, D, C);
        pool_p2_kernel<<<G, D>>>(mean_pool, add_b, add_inv, D, C);
    } else {
        int nsub = 4;
        int thr = nsub * D;
        if (thr > 1024) { nsub = 1024 / D; thr = nsub * D; }
        if (thr < 32) { nsub = 1; thr = D; }
        size_t smem = (size_t)3 * nsub * D * sizeof(float);
        pool_kernel<<<G, thr, smem>>>(embed, a_out, mean_pool, add_b, add_inv, D);
    }
}

// round 8
// speedup vs baseline: 2.3233x; 1.0563x over previous
#include <cuda_runtime.h>
#include <math.h>

// ---------------- scratch (device globals; no allocation) ----------------
#define MAX_M_LOGITS (1 << 18)   // 262144 floats, M = 100000 fits
#define MAX_G 4096
#define SMX_BLOCKS 128
#define POOL_SCRATCH_FLOATS (1 << 22)   // 4M floats = 16 MB partial-sum scratch

__device__ float  g_logits[MAX_M_LOGITS];
__device__ float2 g_ac[MAX_M_LOGITS];          // (a, cgate) packed
__device__ float  g_pmax[SMX_BLOCKS];
__device__ float  g_psum[SMX_BLOCKS];
__device__ int    g_seg[MAX_G + 1];
__device__ float  g_part[POOL_SCRATCH_FLOATS];

// ---------------- embed + logits: warp per motif ----------------
// Per-warp dtype sniff: read K/2 int64s from this warp's own K*4-byte window
// (in-bounds whichever dtype the buffer really is). int32 data seen as int64
// packs two indices per word -> out of [0, n_nodes) with prob ~1.
__global__ __launch_bounds__(256) void embed_kernel(
        const float* __restrict__ n_emb,
        const float* __restrict__ att,
        const void* __restrict__ midx,
        float* __restrict__ embed_out,
        int M, int K, int D, long long n_nodes) {
    int warp = (int)(((long long)blockIdx.x * blockDim.x + threadIdx.x) >> 5);
    int lane = threadIdx.x & 31;
    if (warp >= M) return;

    const long long* mi64 = (const long long*)midx;
    const int*       mi32 = (const int*)midx;

    // dtype sniff (K even; K=16 here)
    int ok = 1;
    if (lane < (K >> 1)) {
        long long v = __ldcs(mi64 + (long long)warp * (K >> 1) + lane);
        ok = (v >= 0 && v < n_nodes) ? 1 : 0;
    }
    const bool is64 = (__all_sync(0xffffffffu, ok) != 0);

    const float invK = 1.0f / (float)K;
    float* eout = embed_out + (long long)warp * D;
    float dot = 0.0f;

    const unsigned rowbytes = (unsigned)(D * 4);
    const bool fit32 = (n_nodes * (long long)rowbytes) < 0x7fffffffLL;

    if ((D & 127) == 0 && fit32) {
        const char* base = (const char*)n_emb;
        unsigned myoff = 0;
        if (lane < K && K <= 32) {
            long long pos = (long long)warp * K + lane;
            long long j = is64 ? __ldcs(mi64 + pos) : (long long)__ldcs(mi32 + pos);
            myoff = (unsigned)j * rowbytes;
        }
        for (int c = 0; c < D; c += 128) {
            float4 attv = ((const float4*)(att + c))[lane];
            float4 acc = make_float4(0.f, 0.f, 0.f, 0.f);
            if (K == 16) {
                #pragma unroll 16
                for (int k = 0; k < 16; k++) {
                    unsigned off = __shfl_sync(0xffffffffu, myoff, k);
                    float4 v = __ldg((const float4*)(base + off + c * 4) + lane);
                    acc.x += v.x; acc.y += v.y; acc.z += v.z; acc.w += v.w;
                }
            } else {
                for (int k0 = 0; k0 < K; k0 += 32) {
                    int kn = min(32, K - k0);
                    unsigned o2 = 0;
                    if (lane < kn) {
                        long long pos = (long long)warp * K + k0 + lane;
                        long long j = is64 ? __ldcs(mi64 + pos) : (long long)__ldcs(mi32 + pos);
                        o2 = (unsigned)j * rowbytes;
                    }
                    for (int k = 0; k < kn; k++) {
                        unsigned off = __shfl_sync(0xffffffffu, o2, k);
                        float4 v = __ldg((const float4*)(base + off + c * 4) + lane);
                        acc.x += v.x; acc.y += v.y; acc.z += v.z; acc.w += v.w;
                    }
                }
            }
            float4 e = make_float4(acc.x * invK, acc.y * invK, acc.z * invK, acc.w * invK);
            __stcs((float4*)(eout + c) + lane, e);   // evict-first: keep table in L2
            dot += e.x * attv.x + e.y * attv.y + e.z * attv.z + e.w * attv.w;
        }
    } else {
        for (int c = 0; c < D; c += 32) {
            int d = c + lane;
            float attv = (d < D) ? att[d] : 0.0f;
            float acc = 0.0f;
            for (int k0 = 0; k0 < K; k0 += 32) {
                int kn = min(32, K - k0);
                long long myidx = 0;
                if (lane < kn) {
                    long long pos = (long long)warp * K + k0 + lane;
                    myidx = is64 ? mi64[pos] : (long long)mi32[pos];
                }
                for (int k = 0; k < kn; k++) {
                    long long j = __shfl_sync(0xffffffffu, myidx, k);
                    if (d < D) acc += __ldg(n_emb + j * (long long)D + d);
                }
            }
            float e = acc * invK;
            if (d < D) { eout[d] = e; dot += e * attv; }
        }
    }

    #pragma unroll
    for (int o = 16; o > 0; o >>= 1) dot += __shfl_xor_sync(0xffffffffu, dot, o);
    if (lane == 0) g_logits[warp] = dot / 10.0f;
}

// ---------------- online softmax: phase 1 (per-block partials) ----------------
__device__ __forceinline__ void smx_merge(float& m1, float& s1, float m2, float s2) {
    float M = fmaxf(m1, m2);
    float s = 0.0f;
    if (M > -3.0e38f) s = s1 * expf(m1 - M) + s2 * expf(m2 - M);
    m1 = M; s1 = s;
}

__global__ void softmax_p1_kernel(int M) {
    const int tid = threadIdx.x;
    const int stride = gridDim.x * blockDim.x;
    int i = blockIdx.x * blockDim.x + tid;

    float mx = -3.402823466e38f, sm = 0.0f;
    for (; i < M; i += stride) {
        float l = g_logits[i];
        if (l > mx) { sm = sm * expf(mx - l) + 1.0f; mx = l; }
        else        { sm += expf(l - mx); }
    }
    #pragma unroll
    for (int o = 16; o > 0; o >>= 1) {
        float om = __shfl_xor_sync(0xffffffffu, mx, o);
        float os = __shfl_xor_sync(0xffffffffu, sm, o);
        smx_merge(mx, sm, om, os);
    }
    __shared__ float smx[8], ssm[8];
    if ((tid & 31) == 0) { smx[tid >> 5] = mx; ssm[tid >> 5] = sm; }
    __syncthreads();
    if (tid < 32) {
        int nw = blockDim.x >> 5;
        float m2 = (tid < nw) ? smx[tid] : -3.402823466e38f;
        float s2 = (tid < nw) ? ssm[tid] : 0.0f;
        #pragma unroll
        for (int o = 16; o > 0; o >>= 1) {
            float om = __shfl_xor_sync(0xffffffffu, m2, o);
            float os = __shfl_xor_sync(0xffffffffu, s2, o);
            smx_merge(m2, s2, om, os);
        }
        if (tid == 0) { g_pmax[blockIdx.x] = m2; g_psum[blockIdx.x] = s2; }
    }
}

// ------- a[m], gate c[m], seg boundaries; fuses the partial combine -------
__global__ __launch_bounds__(256) void a_seg_kernel(
        const void* __restrict__ batch,
        float* __restrict__ a_out, int M, int G) {
    const int tid = threadIdx.x;
    __shared__ float sm_m[4], sm_s[4];
    __shared__ float s_fin[2];
    __shared__ int   s_b64;

    if (tid < SMX_BLOCKS) {
        float m = g_pmax[tid], s = g_psum[tid];
        #pragma unroll
        for (int o = 16; o > 0; o >>= 1) {
            float om = __shfl_xor_sync(0xffffffffu, m, o);
            float os = __shfl_xor_sync(0xffffffffu, s, o);
            smx_merge(m, s, om, os);
        }
        if ((tid & 31) == 0) { sm_m[tid >> 5] = m; sm_s[tid >> 5] = s; }
    }
    // batch dtype sniff from the END of the sorted array (start may be all 0s)
    if (tid >= 128 && tid < 160) {
        int lane = tid & 31;
        int ok = 1;
        if (lane < 8) {
            long long p = (long long)(M >> 1) - 1 - lane;
            if (p >= 0) {
                long long v = ((const long long*)batch)[p];
                ok = (v >= 0 && v < (long long)G) ? 1 : 0;
            }
        }
        unsigned all = __all_sync(0xffffffffu, ok);
        if (lane == 0) s_b64 = all ? 1 : 0;
    }
    __syncthreads();
    if (tid == 0) {
        float m = sm_m[0], s = sm_s[0];
        #pragma unroll
        for (int w = 1; w < 4; w++) smx_merge(m, s, sm_m[w], sm_s[w]);
        s_fin[0] = m; s_fin[1] = 1.0f / s;
    }
    __syncthreads();
    const float gmax = s_fin[0];
    const float ginv = s_fin[1];
    const bool  is64 = (s_b64 != 0);

    int i = blockIdx.x * blockDim.x + tid;
    if (i >= M) return;

    float a = expf(g_logits[i] - gmax) * ginv;
    a_out[i] = a;
    float c = 1.0f / (1.0f + expf(-1000.0f * (a - 0.1f)));
    g_ac[i] = make_float2(a, c);

    const long long* b64 = (const long long*)batch;
    const int*       b32 = (const int*)batch;
    long long b0 = is64 ? b64[i] : (long long)b32[i];
    long long b1 = (i + 1 < M) ? (is64 ? b64[i + 1] : (long long)b32[i + 1])
                               : (long long)G;
    if (i == 0) {
        for (long long v = 0; v <= b0; v++) g_seg[v] = 0;
    }
    for (long long v = b0 + 1; v <= b1; v++) g_seg[v] = i + 1;
}

// ------- pool phase 1: (graph, chunk) grid, warp-per-row, 8 warps/block -------
// Requires D % 4 == 0 and D <= 128.
__global__ __launch_bounds__(256) void pool_p1_kernel(
        const float* __restrict__ embed,
        const float2* __restrict__ ac,
        int D, int C) {
    const int g = blockIdx.x;
    const int c = blockIdx.y;
    const int start = g_seg[g];
    const int end   = g_seg[g + 1];
    const int lane = threadIdx.x & 31;
    const int w    = threadIdx.x >> 5;       // 8 warps
    const int nd4  = D >> 2;

    float4 an = make_float4(0.f, 0.f, 0.f, 0.f);
    float4 ab = an, ae = an;

    if (lane < nd4) {
        for (int m = start + c * 8 + w; m < end; m += C * 8) {
            float2 acm = __ldg(&ac[m]);                   // (a, cgate)
            float4 e = __ldcs((const float4*)(embed + (long long)m * D) + lane);
            an.x += e.x * acm.y; an.y += e.y * acm.y; an.z += e.z * acm.y; an.w += e.w * acm.y;
            ab.x += e.x * acm.x; ab.y += e.y * acm.x; ab.z += e.z * acm.x; ab.w += e.w * acm.x;
            ae.x += e.x;         ae.y += e.y;         ae.z += e.z;         ae.w += e.w;
        }
    }

    extern __shared__ float sred[];          // [8][3][D]
    if (lane < nd4) {
        ((float4*)(sred + (w * 3 + 0) * D))[lane] = an;
        ((float4*)(sred + (w * 3 + 1) * D))[lane] = ab;
        ((float4*)(sred + (w * 3 + 2) * D))[lane] = ae;
    }
    __syncthreads();

    // cross-warp reduce, write this chunk's partial (fixed order: warps 0..7)
    for (int t = threadIdx.x; t < 3 * D; t += blockDim.x) {
        const int r = t / D, d = t % D;
        float s = 0.f;
        #pragma unroll 4
        for (int w2 = 0; w2 < 8; w2++) s += sred[(w2 * 3 + r) * D + d];
        g_part[(((long long)g * C + c) * 3 + r) * D + d] = s;
    }
}

// ---------------- pool phase 2: combine chunk partials ----------------
__global__ void pool_p2_kernel(float* __restrict__ mean_pool,
                               float* __restrict__ add_b,
                               float* __restrict__ add_inv,
                               int D, int C) {
    const int g = blockIdx.x;
    const int d = threadIdx.x;
    if (d >= D) return;
    const int cnt = g_seg[g + 1] - g_seg[g];
    const float inv_cnt = 1.0f / fmaxf((float)cnt, 1.0f);

    float sn = 0.f, sb = 0.f, se = 0.f;
    for (int c = 0; c < C; c++) {
        const float* p = g_part + (((long long)g * C + c) * 3) * D;
        sn += p[d];
        sb += p[D + d];
        se += p[2 * D + d];
    }
    long long o = (long long)g * D + d;
    mean_pool[o] = sn * inv_cnt;
    add_b[o]     = sb;
    add_inv[o]   = se - sb;   // sum e*(1-a) = sum e - sum e*a
}

// ---------------- pool fallback: block per graph (generic D) ----------------
__global__ __launch_bounds__(512) void pool_kernel(
        const float* __restrict__ embed,
        float* __restrict__ mean_pool,
        float* __restrict__ add_b,
        float* __restrict__ add_inv,
        int D) {
    const int g = blockIdx.x;
    const int start = g_seg[g];
    const int end   = g_seg[g + 1];
    const float inv_cnt = 1.0f / fmaxf((float)(end - start), 1.0f);

    const int nsub = blockDim.x / D;
    const int d    = threadIdx.x % D;
    const int sub  = threadIdx.x / D;

    float sn = 0.f, sb = 0.f, se = 0.f;
    for (int m = start + sub; m < end; m += nsub) {
        float2 acm = __ldg(&g_ac[m]);
        float e  = __ldcs(embed + (long long)m * D + d);
        sn += e * acm.y;
        sb += e * acm.x;
        se += e;
    }

    extern __shared__ float sred[];
    float* r_sn = sred;
    float* r_sb = sred + nsub * D;
    float* r_se = sred + 2 * nsub * D;
    r_sn[sub * D + d] = sn;
    r_sb[sub * D + d] = sb;
    r_se[sub * D + d] = se;
    __syncthreads();

    if (sub == 0) {
        for (int s = 1; s < nsub; s++) {
            sn += r_sn[s * D + d];
            sb += r_sb[s * D + d];
            se += r_se[s * D + d];
        }
        long long o = (long long)g * D + d;
        mean_pool[o] = sn * inv_cnt;
        add_b[o]     = sb;
        add_inv[o]   = se - sb;
    }
}

// ---------------- launch ----------------
extern "C" void kernel_launch(void* const* d_in, const int* in_sizes, int n_in,
                              void* d_out, int out_size) {
    const float* n_emb = (const float*)d_in[0];
    const float* att   = (const float*)d_in[1];
    const void*  midx  = d_in[2];
    const void*  batch = d_in[3];

    const int D = in_sizes[1];
    const int M = in_sizes[3];
    const int K = in_sizes[2] / M;
    const long long n_nodes = (long long)in_sizes[0] / D;
    const int G = (int)(((long long)out_size - M - (long long)M * D) / (3LL * D));

    float* out       = (float*)d_out;
    float* a_out     = out;                          // [M]
    float* embed     = a_out + M;                    // [M, D]
    float* mean_pool = embed + (long long)M * D;     // [G, D]
    float* add_b     = mean_pool + (long long)G * D; // [G, D]
    float* add_inv   = add_b + (long long)G * D;     // [G, D]

    // 1) embed + logits (dtype sniff fused, warp per motif)
    {
        int warps_per_block = 8;
        int blocks = (M + warps_per_block - 1) / warps_per_block;
        embed_kernel<<<blocks, warps_per_block * 32>>>(n_emb, att, midx, embed,
                                                       M, K, D, n_nodes);
    }

    // 2) softmax partials
    softmax_p1_kernel<<<SMX_BLOCKS, 256>>>(M);

    // 3) combine + a[m], gate, segment boundaries
    a_seg_kernel<<<(M + 255) / 256, 256>>>(batch, a_out, M, G);

    // 4) segment pooling (deterministic, atomic-free)
    if ((D & 3) == 0 && D <= 128 && G <= MAX_G) {
        int C = 4;
        while (C > 1 && (long long)G * C * 3 * D > POOL_SCRATCH_FLOATS) C >>= 1;
        size_t smem1 = (size_t)8 * 3 * D * sizeof(float);
        float2* ac = nullptr;
        cudaGetSymbolAddress((void**)&ac, g_ac);
        dim3 grid1(G, C);
        pool_p1_kernel<<<grid1, 256, smem1>>>(embed, (const float2*)ac, D, C);
        pool_p2_kernel<<<G, D>>>(mean_pool, add_b, add_inv, D, C);
    } else {
        int nsub = 4;
        int thr = nsub * D;
        if (thr > 1024) { nsub = 1024 / D; thr = nsub * D; }
        if (thr < 32) { nsub = 1; thr = D; }
        size_t smem = (size_t)3 * nsub * D * sizeof(float);
        pool_kernel<<<G, thr, smem>>>(embed, mean_pool, add_b, add_inv, D);
    }
}